// round 3
// baseline (speedup 1.0000x reference)
#include <cuda_runtime.h>
#include <cmath>

// Problem constants
#define B_   1024
#define ZD_  256
#define HD_  1024
#define L_   32
#define NW_  64
#define XD_  1024
#define H3   3072   // 3*HD

// ---------------- scratch (device globals: no runtime allocation) ----------
__device__ float g_GXALL[(size_t)L_ * B_ * H3];   // gx for all steps   (~403 MB)
__device__ float g_GH[(size_t)B_ * H3];           // gh for current step (~12.6 MB)
__device__ float g_ZT[(size_t)L_ * B_ * HD_];     // z_theta per step    (~134 MB)
__device__ float g_A1[(size_t)L_ * B_ * HD_];     // MLP hidden per step (~134 MB)

// ---------------- helpers ---------------------------------------------------
__device__ __forceinline__ float sigf(float x) { return 1.0f / (1.0f + expf(-x)); }

struct GP {
    const float* A;    size_t sA; int lda;   // [M,K] row-major, per-l stride sA
    const float* Bm;   size_t sB; int ldb;   // [N,K] row-major, per-l stride sB
    float*       C;    size_t sC; int ldc;
    const float* bias; size_t sBias;
    const float* tmat;                       // t [B,L], mode 1 only
    int M, N, K, mode;
    // mode 0: C = acc + bias
    // mode 1: C = acc + bias + t[m,l] * Bm[n*ldb + K]   (rank-1 from Wih last col)
    // mode 2: C = relu(acc + bias)
    // mode 3: C = sigmoid(acc + bias)
    // mode 4: out[(n*B + m)*L + l] = sigmoid(acc + bias)   (transposed preds)
};

// NT GEMM: C[m,n] = sum_k A[m,k]*B[n,k]  — 128x128x16 tile, 8x8 per thread.
template <bool VECB>
__global__ __launch_bounds__(256, 2)
void gemm_nt(GP p) {
    constexpr int BM = 128, BN = 128, BK = 16;
    __shared__ float As[BK][BM + 4];
    __shared__ float Bs[BK][BN + 4];

    const int l = blockIdx.z;
    const float* A    = p.A    + (size_t)l * p.sA;
    const float* Bm   = p.Bm   + (size_t)l * p.sB;
    const float* bias = p.bias + (size_t)l * p.sBias;
    float*       C    = p.C    + (size_t)l * p.sC;

    const int m0 = blockIdx.y * BM;
    const int n0 = blockIdx.x * BN;
    const int tid = threadIdx.x;
    const int lr = tid >> 2;          // 0..63
    const int lc = (tid & 3) << 2;    // 0,4,8,12

    float acc[8][8];
#pragma unroll
    for (int i = 0; i < 8; i++)
#pragma unroll
        for (int j = 0; j < 8; j++) acc[i][j] = 0.0f;

    for (int k0 = 0; k0 < p.K; k0 += BK) {
        // A tile (always vectorizable in our uses: lda % 4 == 0)
#pragma unroll
        for (int h = 0; h < 2; h++) {
            const int m = m0 + lr + h * 64;
            float4 v = *reinterpret_cast<const float4*>(&A[(size_t)m * p.lda + k0 + lc]);
            As[lc + 0][lr + h * 64] = v.x;
            As[lc + 1][lr + h * 64] = v.y;
            As[lc + 2][lr + h * 64] = v.z;
            As[lc + 3][lr + h * 64] = v.w;
        }
        // B tile (scalar path for ldb=257 of Wih; bounds guard for N=64)
#pragma unroll
        for (int h = 0; h < 2; h++) {
            const int n = n0 + lr + h * 64;
            float4 v = make_float4(0.f, 0.f, 0.f, 0.f);
            if (n < p.N) {
                const float* bp = &Bm[(size_t)n * p.ldb + k0 + lc];
                if (VECB) {
                    v = *reinterpret_cast<const float4*>(bp);
                } else {
                    v.x = bp[0]; v.y = bp[1]; v.z = bp[2]; v.w = bp[3];
                }
            }
            Bs[lc + 0][lr + h * 64] = v.x;
            Bs[lc + 1][lr + h * 64] = v.y;
            Bs[lc + 2][lr + h * 64] = v.z;
            Bs[lc + 3][lr + h * 64] = v.w;
        }
        __syncthreads();

        const int tx = tid & 15, ty = tid >> 4;
#pragma unroll
        for (int k = 0; k < BK; k++) {
            float a[8], b[8];
            *reinterpret_cast<float4*>(&a[0]) = *reinterpret_cast<const float4*>(&As[k][ty * 8]);
            *reinterpret_cast<float4*>(&a[4]) = *reinterpret_cast<const float4*>(&As[k][ty * 8 + 4]);
            *reinterpret_cast<float4*>(&b[0]) = *reinterpret_cast<const float4*>(&Bs[k][tx * 8]);
            *reinterpret_cast<float4*>(&b[4]) = *reinterpret_cast<const float4*>(&Bs[k][tx * 8 + 4]);
#pragma unroll
            for (int i = 0; i < 8; i++)
#pragma unroll
                for (int j = 0; j < 8; j++)
                    acc[i][j] = fmaf(a[i], b[j], acc[i][j]);
        }
        __syncthreads();
    }

    // Epilogue
    const int tx = tid & 15, ty = tid >> 4;
    const int mb = m0 + ty * 8, nb = n0 + tx * 8;

    if (p.mode == 1) {
#pragma unroll
        for (int i = 0; i < 8; i++) {
            const float tv = p.tmat[(size_t)(mb + i) * L_ + l];
#pragma unroll
            for (int j = 0; j < 8; j++) {
                const int n = nb + j;
                const float wt = Bm[(size_t)n * p.ldb + p.K];
                C[(size_t)(mb + i) * p.ldc + n] = acc[i][j] + bias[n] + tv * wt;
            }
        }
    } else if (p.mode == 0) {
#pragma unroll
        for (int i = 0; i < 8; i++)
#pragma unroll
            for (int j = 0; j < 8; j++) {
                const int n = nb + j;
                C[(size_t)(mb + i) * p.ldc + n] = acc[i][j] + bias[n];
            }
    } else if (p.mode == 2) {
#pragma unroll
        for (int i = 0; i < 8; i++)
#pragma unroll
            for (int j = 0; j < 8; j++) {
                const int n = nb + j;
                C[(size_t)(mb + i) * p.ldc + n] = fmaxf(acc[i][j] + bias[n], 0.0f);
            }
    } else if (p.mode == 3) {
#pragma unroll
        for (int i = 0; i < 8; i++)
#pragma unroll
            for (int j = 0; j < 8; j++) {
                const int n = nb + j;
                C[(size_t)(mb + i) * p.ldc + n] = sigf(acc[i][j] + bias[n]);
            }
    } else { // mode 4: transposed preds store  out[(n*B + m)*L + l]
#pragma unroll
        for (int i = 0; i < 8; i++)
#pragma unroll
            for (int j = 0; j < 8; j++) {
                const int n = nb + j;
                if (n < p.N)
                    p.C[((size_t)n * B_ + (mb + i)) * L_ + l] = sigf(acc[i][j] + bias[n]);
            }
    }
}

// Fused GRU gate: z_theta = (1-u)*n + u*h + std*eps
__device__ __forceinline__ float gru_one(float xr, float xu, float xn,
                                         float hr, float hu, float hn,
                                         float hp, float ep) {
    const float STD = 1.0025031276057952f; // exp(0.5*0.005)
    float r = sigf(xr + hr);
    float u = sigf(xu + hu);
    float n = tanhf(xn + r * hn);
    return (1.0f - u) * n + u * hp + STD * ep;
}

__global__ void gru_gate(const float* __restrict__ gx, const float* __restrict__ gh,
                         const float* __restrict__ bhh, const float* __restrict__ hprev,
                         const float* __restrict__ eps, float* __restrict__ hnew,
                         int first) {
    const int i4 = blockIdx.x * blockDim.x + threadIdx.x;
    if (i4 >= B_ * HD_ / 4) return;
    const int idx = i4 << 2;
    const int b = idx >> 10;          // /HD_
    const int j = idx & (HD_ - 1);
    const size_t o3 = (size_t)b * H3 + j;
    const size_t o1 = (size_t)b * HD_ + j;

    float4 xr = *reinterpret_cast<const float4*>(&gx[o3]);
    float4 xu = *reinterpret_cast<const float4*>(&gx[o3 + HD_]);
    float4 xn = *reinterpret_cast<const float4*>(&gx[o3 + 2 * HD_]);
    float4 hr, hu, hn, hp;
    if (first) {
        hr = *reinterpret_cast<const float4*>(&bhh[j]);
        hu = *reinterpret_cast<const float4*>(&bhh[j + HD_]);
        hn = *reinterpret_cast<const float4*>(&bhh[j + 2 * HD_]);
        hp = make_float4(0.f, 0.f, 0.f, 0.f);
    } else {
        hr = *reinterpret_cast<const float4*>(&gh[o3]);
        hu = *reinterpret_cast<const float4*>(&gh[o3 + HD_]);
        hn = *reinterpret_cast<const float4*>(&gh[o3 + 2 * HD_]);
        hp = *reinterpret_cast<const float4*>(&hprev[o1]);
    }
    float4 ep = *reinterpret_cast<const float4*>(&eps[o1]);

    float4 o;
    o.x = gru_one(xr.x, xu.x, xn.x, hr.x, hu.x, hn.x, hp.x, ep.x);
    o.y = gru_one(xr.y, xu.y, xn.y, hr.y, hu.y, hn.y, hp.y, ep.y);
    o.z = gru_one(xr.z, xu.z, xn.z, hr.z, hu.z, hn.z, hp.z, ep.z);
    o.w = gru_one(xr.w, xu.w, xn.w, hr.w, hu.w, hn.w, hp.w, ep.w);
    *reinterpret_cast<float4*>(&hnew[o1]) = o;
}

// ---------------- launch ----------------------------------------------------
extern "C" void kernel_launch(void* const* d_in, const int* in_sizes, int n_in,
                              void* d_out, int out_size) {
    const float* z    = (const float*)d_in[0];
    const float* t    = (const float*)d_in[1];
    const float* eps  = (const float*)d_in[2];
    const float* Wih  = (const float*)d_in[3];
    const float* Whh  = (const float*)d_in[4];
    const float* bih  = (const float*)d_in[5];
    const float* bhh  = (const float*)d_in[6];
    const float* pW1  = (const float*)d_in[7];
    const float* pb1  = (const float*)d_in[8];
    const float* pW2  = (const float*)d_in[9];
    const float* pb2  = (const float*)d_in[10];
    const float* recW = (const float*)d_in[11];
    const float* recb = (const float*)d_in[12];

    float* out       = (float*)d_out;
    float* out_recon = out;                          // [B, XD]
    float* out_pred  = out + (size_t)B_ * XD_;       // [NW, B, L]

    float *GX, *GH, *ZT, *A1;
    cudaGetSymbolAddress((void**)&GX, g_GXALL);
    cudaGetSymbolAddress((void**)&GH, g_GH);
    cudaGetSymbolAddress((void**)&ZT, g_ZT);
    cudaGetSymbolAddress((void**)&A1, g_A1);

    // 1) gx_all[l] = z @ WihZ_l^T + t[:,l] ⊗ Wih_l[:,ZD] + bih_l   (L-parallel)
    {
        GP p{};
        p.A = z;   p.sA = 0;                        p.lda = ZD_;
        p.Bm = Wih; p.sB = (size_t)H3 * (ZD_ + 1);  p.ldb = ZD_ + 1;
        p.C = GX;  p.sC = (size_t)B_ * H3;          p.ldc = H3;
        p.bias = bih; p.sBias = H3;
        p.tmat = t;
        p.M = B_; p.N = H3; p.K = ZD_; p.mode = 1;
        gemm_nt<false><<<dim3(H3 / 128, B_ / 128, L_), 256>>>(p);
    }

    // 2) sequential GRU scan: gh = h @ Whh_l^T + bhh; fused gates -> z_theta
    for (int l = 0; l < L_; l++) {
        const float* hprev = (l == 0) ? nullptr : (ZT + (size_t)(l - 1) * B_ * HD_);
        if (l > 0) {
            GP p{};
            p.A = hprev;                    p.sA = 0; p.lda = HD_;
            p.Bm = Whh + (size_t)l * H3 * HD_; p.sB = 0; p.ldb = HD_;
            p.C = GH;                       p.sC = 0; p.ldc = H3;
            p.bias = bhh + (size_t)l * H3;  p.sBias = 0;
            p.M = B_; p.N = H3; p.K = HD_; p.mode = 0;
            gemm_nt<true><<<dim3(H3 / 128, B_ / 128, 1), 256>>>(p);
        }
        gru_gate<<<(B_ * HD_ / 4 + 255) / 256, 256>>>(
            GX + (size_t)l * B_ * H3, GH, bhh + (size_t)l * H3, hprev,
            eps + (size_t)l * B_ * HD_, ZT + (size_t)l * B_ * HD_, (l == 0) ? 1 : 0);
    }

    // 3) MLP hidden: A1[l] = relu(z_theta[l] @ pW1_l^T + pb1_l)   (L-parallel)
    {
        GP p{};
        p.A = ZT;  p.sA = (size_t)B_ * HD_;  p.lda = HD_;
        p.Bm = pW1; p.sB = (size_t)HD_ * HD_; p.ldb = HD_;
        p.C = A1;  p.sC = (size_t)B_ * HD_;  p.ldc = HD_;
        p.bias = pb1; p.sBias = HD_;
        p.M = B_; p.N = HD_; p.K = HD_; p.mode = 2;
        gemm_nt<true><<<dim3(HD_ / 128, B_ / 128, L_), 256>>>(p);
    }

    // 4) preds: sigmoid(A1[l] @ pW2_l^T + pb2_l), stored [NW, B, L]   (L-parallel)
    {
        GP p{};
        p.A = A1;  p.sA = (size_t)B_ * HD_;  p.lda = HD_;
        p.Bm = pW2; p.sB = (size_t)NW_ * HD_; p.ldb = HD_;
        p.C = out_pred; p.sC = 0; p.ldc = 0;
        p.bias = pb2; p.sBias = NW_;
        p.M = B_; p.N = NW_; p.K = HD_; p.mode = 4;
        gemm_nt<true><<<dim3(1, B_ / 128, L_), 256>>>(p);
    }

    // 5) recon = sigmoid(hT @ recW^T + recb)
    {
        GP p{};
        p.A = ZT + (size_t)(L_ - 1) * B_ * HD_; p.sA = 0; p.lda = HD_;
        p.Bm = recW; p.sB = 0; p.ldb = HD_;
        p.C = out_recon; p.sC = 0; p.ldc = XD_;
        p.bias = recb; p.sBias = 0;
        p.M = B_; p.N = XD_; p.K = HD_; p.mode = 3;
        gemm_nt<true><<<dim3(XD_ / 128, B_ / 128, 1), 256>>>(p);
    }
}

// round 4
// speedup vs baseline: 2.5789x; 2.5789x over previous
#include <cuda_runtime.h>
#include <cmath>
#include <cstdint>

// Problem constants
#define B_   1024
#define ZD_  256
#define HD_  1024
#define L_   32
#define NW_  64
#define XD_  1024
#define H3   3072   // 3*HD

// ---------------- scratch (device globals: no runtime allocation) ----------
__device__ float g_GXALL[(size_t)L_ * B_ * H3];   // gx for all steps
__device__ float g_GH[(size_t)B_ * H3];           // gh for current step
__device__ float g_ZT[(size_t)L_ * B_ * HD_];     // z_theta per step
__device__ float g_A1[(size_t)L_ * B_ * HD_];     // MLP hidden per step

// ---------------- helpers ---------------------------------------------------
__device__ __forceinline__ float sigf(float x) { return 1.0f / (1.0f + expf(-x)); }

__device__ __forceinline__ float to_tf32(float x) {
    float r;
    asm("cvt.rna.tf32.f32 %0, %1;" : "=f"(r) : "f"(x));
    return r;
}

__device__ __forceinline__ void ldsm4(uint32_t* r, const void* p) {
    uint32_t a = (uint32_t)__cvta_generic_to_shared(p);
    asm volatile("ldmatrix.sync.aligned.m8n8.x4.shared.b16 {%0,%1,%2,%3}, [%4];"
                 : "=r"(r[0]), "=r"(r[1]), "=r"(r[2]), "=r"(r[3]) : "r"(a));
}

__device__ __forceinline__ void mma8(float* c, const uint32_t* a, uint32_t b0, uint32_t b1) {
    asm volatile("mma.sync.aligned.m16n8k8.row.col.f32.tf32.tf32.f32 "
                 "{%0,%1,%2,%3}, {%4,%5,%6,%7}, {%8,%9}, {%0,%1,%2,%3};"
                 : "+f"(c[0]), "+f"(c[1]), "+f"(c[2]), "+f"(c[3])
                 : "r"(a[0]), "r"(a[1]), "r"(a[2]), "r"(a[3]), "r"(b0), "r"(b1));
}

struct GP {
    const float* A;    size_t sA; int lda;   // [M,K] row-major, per-l stride sA
    const float* Bm;   size_t sB; int ldb;   // [N,K] row-major, per-l stride sB
    float*       C;    size_t sC; int ldc;
    const float* bias; size_t sBias;
    const float* tmat;                       // t [B,L], mode 1 only
    int M, N, K, mode;
    // mode 0: C = acc + bias
    // mode 1: C = acc + bias + t[m,l] * Bm[n*ldb + K]   (rank-1 from Wih last col)
    // mode 2: C = relu(acc + bias)
    // mode 3: C = sigmoid(acc + bias)
    // mode 4: out[(n*B + m)*L + l] = sigmoid(acc + bias)   (transposed preds)
};

// TF32 NT GEMM: C[m,n] = sum_k A[m,k]*B[n,k]
// 128x128 block tile, 256 threads = 8 warps (2m x 4n), warp tile 64x32,
// per-warp 4 m16 tiles x 4 n8 tiles of m16n8k8 tf32 mma. BK=16.
template <bool VECB>
__global__ __launch_bounds__(256)
void gemm_tf32(GP p) {
    constexpr int BK = 16;
    __shared__ float As[128][20];   // pad to 20 floats (80B): LDSM conflict-free
    __shared__ float Bs[128][20];

    const int l = blockIdx.z;
    const float* A    = p.A    + (size_t)l * p.sA;
    const float* Bm   = p.Bm   + (size_t)l * p.sB;
    const float* bias = p.bias + (size_t)l * p.sBias;

    const int m0 = blockIdx.y * 128;
    const int n0 = blockIdx.x * 128;
    const int tid = threadIdx.x;
    const int lane = tid & 31;
    const int warp = tid >> 5;
    const int wm = warp >> 2;        // 0..1
    const int wn = warp & 3;         // 0..3

    // staging: each thread loads 2 float4 rows for A and B
    const int srow = tid >> 2;       // 0..63
    const int scol = (tid & 3) * 4;  // 0,4,8,12

    float acc[16][4];
#pragma unroll
    for (int i = 0; i < 16; i++) {
        acc[i][0] = acc[i][1] = acc[i][2] = acc[i][3] = 0.0f;
    }

    float ra[2][4], rb[2][4];
    const int nIter = p.K / BK;

    auto gload = [&](int k0) {
#pragma unroll
        for (int h = 0; h < 2; h++) {
            const int m = m0 + srow + h * 64;
            const float* s = &A[(size_t)m * p.lda + k0 + scol];
            float4 v = *reinterpret_cast<const float4*>(s);
            ra[h][0] = to_tf32(v.x); ra[h][1] = to_tf32(v.y);
            ra[h][2] = to_tf32(v.z); ra[h][3] = to_tf32(v.w);

            const int n = n0 + srow + h * 64;
            if (n < p.N) {
                const float* q = &Bm[(size_t)n * p.ldb + k0 + scol];
                if (VECB) {
                    float4 w = *reinterpret_cast<const float4*>(q);
                    rb[h][0] = to_tf32(w.x); rb[h][1] = to_tf32(w.y);
                    rb[h][2] = to_tf32(w.z); rb[h][3] = to_tf32(w.w);
                } else {
                    rb[h][0] = to_tf32(q[0]); rb[h][1] = to_tf32(q[1]);
                    rb[h][2] = to_tf32(q[2]); rb[h][3] = to_tf32(q[3]);
                }
            } else {
                rb[h][0] = rb[h][1] = rb[h][2] = rb[h][3] = 0.0f;
            }
        }
    };
    auto sstore = [&]() {
#pragma unroll
        for (int h = 0; h < 2; h++) {
            *reinterpret_cast<float4*>(&As[srow + h * 64][scol]) =
                make_float4(ra[h][0], ra[h][1], ra[h][2], ra[h][3]);
            *reinterpret_cast<float4*>(&Bs[srow + h * 64][scol]) =
                make_float4(rb[h][0], rb[h][1], rb[h][2], rb[h][3]);
        }
    };

    gload(0);
    sstore();
    __syncthreads();

    // LDSM per-lane source rows/cols (fragment layouts, see mma m16n8k8.tf32)
    const int arow = wm * 64 + (lane & 7) + ((lane >> 3) & 1) * 8;
    const int akc0 = ((lane >> 4) & 1) * 4;
    const int brow = wn * 32 + (lane & 7) + ((lane >> 4) & 1) * 8;
    const int bkc0 = ((lane >> 3) & 1) * 4;

    for (int it = 0; it < nIter; it++) {
        if (it + 1 < nIter) gload((it + 1) * BK);
#pragma unroll
        for (int ks = 0; ks < 2; ks++) {
            uint32_t af[4][4], bf[2][4];
#pragma unroll
            for (int mt = 0; mt < 4; mt++)
                ldsm4(af[mt], &As[arow + mt * 16][ks * 8 + akc0]);
#pragma unroll
            for (int bt = 0; bt < 2; bt++)
                ldsm4(bf[bt], &Bs[brow + bt * 16][ks * 8 + bkc0]);
#pragma unroll
            for (int mt = 0; mt < 4; mt++)
#pragma unroll
                for (int nt = 0; nt < 4; nt++)
                    mma8(acc[mt * 4 + nt], af[mt],
                         bf[nt >> 1][(nt & 1) * 2], bf[nt >> 1][(nt & 1) * 2 + 1]);
        }
        if (it + 1 < nIter) {
            __syncthreads();
            sstore();
            __syncthreads();
        }
    }

    // ---------------- epilogue ----------------
    float* C = p.C + (size_t)l * p.sC;
#pragma unroll
    for (int mt = 0; mt < 4; mt++) {
        const int r = m0 + wm * 64 + mt * 16 + (lane >> 2);   // rows r, r+8
#pragma unroll
        for (int nt = 0; nt < 4; nt++) {
            const int c = n0 + wn * 32 + nt * 8 + 2 * (lane & 3);  // cols c, c+1
            float* a = acc[mt * 4 + nt];
            if (p.mode == 4 && c >= p.N) continue;

            float b0 = bias[c], b1 = bias[c + 1];
            float v00 = a[0] + b0, v01 = a[1] + b1;
            float v10 = a[2] + b0, v11 = a[3] + b1;

            if (p.mode == 1) {
                const float w0 = Bm[(size_t)c * p.ldb + p.K];
                const float w1 = Bm[(size_t)(c + 1) * p.ldb + p.K];
                const float t0 = p.tmat[(size_t)r * L_ + l];
                const float t1 = p.tmat[(size_t)(r + 8) * L_ + l];
                v00 += t0 * w0; v01 += t0 * w1;
                v10 += t1 * w0; v11 += t1 * w1;
            } else if (p.mode == 2) {
                v00 = fmaxf(v00, 0.f); v01 = fmaxf(v01, 0.f);
                v10 = fmaxf(v10, 0.f); v11 = fmaxf(v11, 0.f);
            } else if (p.mode == 3) {
                v00 = sigf(v00); v01 = sigf(v01);
                v10 = sigf(v10); v11 = sigf(v11);
            } else if (p.mode == 4) {
                v00 = sigf(v00); v01 = sigf(v01);
                v10 = sigf(v10); v11 = sigf(v11);
                p.C[((size_t)c       * B_ + r)     * L_ + l] = v00;
                p.C[((size_t)(c + 1) * B_ + r)     * L_ + l] = v01;
                p.C[((size_t)c       * B_ + r + 8) * L_ + l] = v10;
                p.C[((size_t)(c + 1) * B_ + r + 8) * L_ + l] = v11;
                continue;
            }
            *reinterpret_cast<float2*>(&C[(size_t)r * p.ldc + c]) = make_float2(v00, v01);
            *reinterpret_cast<float2*>(&C[(size_t)(r + 8) * p.ldc + c]) = make_float2(v10, v11);
        }
    }
}

// ---------------- fused GRU gate --------------------------------------------
__device__ __forceinline__ float gru_one(float xr, float xu, float xn,
                                         float hr, float hu, float hn,
                                         float hp, float ep) {
    const float STD = 1.0025031276057952f; // exp(0.5*0.005)
    float r = sigf(xr + hr);
    float u = sigf(xu + hu);
    float n = tanhf(xn + r * hn);
    return (1.0f - u) * n + u * hp + STD * ep;
}

__global__ void gru_gate(const float* __restrict__ gx, const float* __restrict__ gh,
                         const float* __restrict__ bhh, const float* __restrict__ hprev,
                         const float* __restrict__ eps, float* __restrict__ hnew,
                         int first) {
    const int i4 = blockIdx.x * blockDim.x + threadIdx.x;
    if (i4 >= B_ * HD_ / 4) return;
    const int idx = i4 << 2;
    const int b = idx >> 10;          // /HD_
    const int j = idx & (HD_ - 1);
    const size_t o3 = (size_t)b * H3 + j;
    const size_t o1 = (size_t)b * HD_ + j;

    float4 xr = *reinterpret_cast<const float4*>(&gx[o3]);
    float4 xu = *reinterpret_cast<const float4*>(&gx[o3 + HD_]);
    float4 xn = *reinterpret_cast<const float4*>(&gx[o3 + 2 * HD_]);
    float4 hr, hu, hn, hp;
    if (first) {
        hr = *reinterpret_cast<const float4*>(&bhh[j]);
        hu = *reinterpret_cast<const float4*>(&bhh[j + HD_]);
        hn = *reinterpret_cast<const float4*>(&bhh[j + 2 * HD_]);
        hp = make_float4(0.f, 0.f, 0.f, 0.f);
    } else {
        hr = *reinterpret_cast<const float4*>(&gh[o3]);
        hu = *reinterpret_cast<const float4*>(&gh[o3 + HD_]);
        hn = *reinterpret_cast<const float4*>(&gh[o3 + 2 * HD_]);
        hp = *reinterpret_cast<const float4*>(&hprev[o1]);
    }
    float4 ep = *reinterpret_cast<const float4*>(&eps[o1]);

    float4 o;
    o.x = gru_one(xr.x, xu.x, xn.x, hr.x, hu.x, hn.x, hp.x, ep.x);
    o.y = gru_one(xr.y, xu.y, xn.y, hr.y, hu.y, hn.y, hp.y, ep.y);
    o.z = gru_one(xr.z, xu.z, xn.z, hr.z, hu.z, hn.z, hp.z, ep.z);
    o.w = gru_one(xr.w, xu.w, xn.w, hr.w, hu.w, hn.w, hp.w, ep.w);
    *reinterpret_cast<float4*>(&hnew[o1]) = o;
}

// ---------------- launch ----------------------------------------------------
extern "C" void kernel_launch(void* const* d_in, const int* in_sizes, int n_in,
                              void* d_out, int out_size) {
    const float* z    = (const float*)d_in[0];
    const float* t    = (const float*)d_in[1];
    const float* eps  = (const float*)d_in[2];
    const float* Wih  = (const float*)d_in[3];
    const float* Whh  = (const float*)d_in[4];
    const float* bih  = (const float*)d_in[5];
    const float* bhh  = (const float*)d_in[6];
    const float* pW1  = (const float*)d_in[7];
    const float* pb1  = (const float*)d_in[8];
    const float* pW2  = (const float*)d_in[9];
    const float* pb2  = (const float*)d_in[10];
    const float* recW = (const float*)d_in[11];
    const float* recb = (const float*)d_in[12];

    float* out       = (float*)d_out;
    float* out_recon = out;                          // [B, XD]
    float* out_pred  = out + (size_t)B_ * XD_;       // [NW, B, L]

    float *GX, *GH, *ZT, *A1;
    cudaGetSymbolAddress((void**)&GX, g_GXALL);
    cudaGetSymbolAddress((void**)&GH, g_GH);
    cudaGetSymbolAddress((void**)&ZT, g_ZT);
    cudaGetSymbolAddress((void**)&A1, g_A1);

    // 1) gx_all[l] = z @ WihZ_l^T + t[:,l] ⊗ Wih_l[:,ZD] + bih_l   (L-parallel)
    {
        GP p{};
        p.A = z;   p.sA = 0;                        p.lda = ZD_;
        p.Bm = Wih; p.sB = (size_t)H3 * (ZD_ + 1);  p.ldb = ZD_ + 1;
        p.C = GX;  p.sC = (size_t)B_ * H3;          p.ldc = H3;
        p.bias = bih; p.sBias = H3;
        p.tmat = t;
        p.M = B_; p.N = H3; p.K = ZD_; p.mode = 1;
        gemm_tf32<false><<<dim3(H3 / 128, B_ / 128, L_), 256>>>(p);
    }

    // 2) sequential GRU scan: gh = h @ Whh_l^T + bhh; fused gates -> z_theta
    for (int l = 0; l < L_; l++) {
        const float* hprev = (l == 0) ? nullptr : (ZT + (size_t)(l - 1) * B_ * HD_);
        if (l > 0) {
            GP p{};
            p.A = hprev;                    p.sA = 0; p.lda = HD_;
            p.Bm = Whh + (size_t)l * H3 * HD_; p.sB = 0; p.ldb = HD_;
            p.C = GH;                       p.sC = 0; p.ldc = H3;
            p.bias = bhh + (size_t)l * H3;  p.sBias = 0;
            p.M = B_; p.N = H3; p.K = HD_; p.mode = 0;
            gemm_tf32<true><<<dim3(H3 / 128, B_ / 128, 1), 256>>>(p);
        }
        gru_gate<<<(B_ * HD_ / 4 + 255) / 256, 256>>>(
            GX + (size_t)l * B_ * H3, GH, bhh + (size_t)l * H3, hprev,
            eps + (size_t)l * B_ * HD_, ZT + (size_t)l * B_ * HD_, (l == 0) ? 1 : 0);
    }

    // 3) MLP hidden: A1[l] = relu(z_theta[l] @ pW1_l^T + pb1_l)   (L-parallel)
    {
        GP p{};
        p.A = ZT;  p.sA = (size_t)B_ * HD_;  p.lda = HD_;
        p.Bm = pW1; p.sB = (size_t)HD_ * HD_; p.ldb = HD_;
        p.C = A1;  p.sC = (size_t)B_ * HD_;  p.ldc = HD_;
        p.bias = pb1; p.sBias = HD_;
        p.M = B_; p.N = HD_; p.K = HD_; p.mode = 2;
        gemm_tf32<true><<<dim3(HD_ / 128, B_ / 128, L_), 256>>>(p);
    }

    // 4) preds: sigmoid(A1[l] @ pW2_l^T + pb2_l), stored [NW, B, L]   (L-parallel)
    {
        GP p{};
        p.A = A1;  p.sA = (size_t)B_ * HD_;  p.lda = HD_;
        p.Bm = pW2; p.sB = (size_t)NW_ * HD_; p.ldb = HD_;
        p.C = out_pred; p.sC = 0; p.ldc = 0;
        p.bias = pb2; p.sBias = NW_;
        p.M = B_; p.N = NW_; p.K = HD_; p.mode = 4;
        gemm_tf32<true><<<dim3(1, B_ / 128, L_), 256>>>(p);
    }

    // 5) recon = sigmoid(hT @ recW^T + recb)
    {
        GP p{};
        p.A = ZT + (size_t)(L_ - 1) * B_ * HD_; p.sA = 0; p.lda = HD_;
        p.Bm = recW; p.sB = 0; p.ldb = HD_;
        p.C = out_recon; p.sC = 0; p.ldc = XD_;
        p.bias = recb; p.sBias = 0;
        p.M = B_; p.N = XD_; p.K = HD_; p.mode = 3;
        gemm_tf32<true><<<dim3(XD_ / 128, B_ / 128, 1), 256>>>(p);
    }
}

// round 5
// speedup vs baseline: 3.1510x; 1.2218x over previous
#include <cuda_runtime.h>
#include <cmath>
#include <cstdint>

// Problem constants
#define B_   1024
#define ZD_  256
#define HD_  1024
#define L_   32
#define NW_  64
#define XD_  1024
#define H3   3072   // 3*HD

// ---------------- scratch (device globals: no runtime allocation) ----------
__device__ float g_GXALL[(size_t)L_ * B_ * H3];   // gx for all steps
__device__ float g_ZT[(size_t)L_ * B_ * HD_];     // z_theta per step (tf32-rounded)
__device__ float g_A1[(size_t)L_ * B_ * HD_];     // MLP hidden per step

// ---------------- helpers ---------------------------------------------------
__device__ __forceinline__ float sigf(float x) { return 1.0f / (1.0f + expf(-x)); }

__device__ __forceinline__ float to_tf32(float x) {
    float r;
    asm("cvt.rna.tf32.f32 %0, %1;" : "=f"(r) : "f"(x));
    return r;
}

__device__ __forceinline__ void ldsm4(uint32_t* r, const void* p) {
    uint32_t a = (uint32_t)__cvta_generic_to_shared(p);
    asm volatile("ldmatrix.sync.aligned.m8n8.x4.shared.b16 {%0,%1,%2,%3}, [%4];"
                 : "=r"(r[0]), "=r"(r[1]), "=r"(r[2]), "=r"(r[3]) : "r"(a));
}

__device__ __forceinline__ void mma8(float* c, const uint32_t* a, uint32_t b0, uint32_t b1) {
    asm volatile("mma.sync.aligned.m16n8k8.row.col.f32.tf32.tf32.f32 "
                 "{%0,%1,%2,%3}, {%4,%5,%6,%7}, {%8,%9}, {%0,%1,%2,%3};"
                 : "+f"(c[0]), "+f"(c[1]), "+f"(c[2]), "+f"(c[3])
                 : "r"(a[0]), "r"(a[1]), "r"(a[2]), "r"(a[3]), "r"(b0), "r"(b1));
}

__device__ __forceinline__ void cpa16(void* dst, const void* src) {
    uint32_t d = (uint32_t)__cvta_generic_to_shared(dst);
    asm volatile("cp.async.cg.shared.global [%0], [%1], 16;" :: "r"(d), "l"(src));
}

// ============================================================================
// Fused GRU step: z_theta = gate( gx_l, h @ Whh_l^T + bhh_l, h, eps_l )
// Grid: (HD/64, B/128) = 128 CTAs (one full wave). 256 threads, 8 warps (2m x 4n).
// Per CTA: 128 rows of B x 64 cols of HD, all 3 gates. cp.async 2-stage, BK=32.
// ============================================================================
#define GRU_BK    32
#define GRU_PAD   36                      // floats per smem row (conflict-free ldsm)
#define GRU_STAGE ((128 + 192) * GRU_PAD) // floats per stage: A[128][36] + B[192][36]
#define GRU_SMEM  (2 * GRU_STAGE * 4)     // bytes = 92160

__global__ __launch_bounds__(256)
void gemm_gru(const float* __restrict__ h,      // [B, HD] prev z_theta (tf32-rounded)
              const float* __restrict__ Whh_l,  // [3*HD, HD]
              const float* __restrict__ bhh_l,  // [3*HD]
              const float* __restrict__ gx_l,   // [B, 3*HD]
              const float* __restrict__ eps_l,  // [B, HD]
              float* __restrict__ zt_out)       // [B, HD]
{
    extern __shared__ float smem[];
    const int n0 = blockIdx.x * 64;
    const int m0 = blockIdx.y * 128;
    const int tid = threadIdx.x;
    const int lane = tid & 31;
    const int warp = tid >> 5;
    const int wm = warp >> 2;   // 0..1
    const int wn = warp & 3;    // 0..3

    float acc[3][8][4];
#pragma unroll
    for (int g = 0; g < 3; g++)
#pragma unroll
        for (int i = 0; i < 8; i++)
            acc[g][i][0] = acc[g][i][1] = acc[g][i][2] = acc[g][i][3] = 0.0f;

    auto issue = [&](int it) {
        float* As = smem + (it & 1) * GRU_STAGE;
        float* Bs = As + 128 * GRU_PAD;
        const int k0 = it * GRU_BK;
#pragma unroll
        for (int i = 0; i < 4; i++) {                 // A: 128 rows x 8 chunks
            const int idx = tid + i * 256;
            const int r = idx >> 3, c = idx & 7;
            cpa16(&As[r * GRU_PAD + c * 4], &h[(size_t)(m0 + r) * HD_ + k0 + c * 4]);
        }
#pragma unroll
        for (int i = 0; i < 6; i++) {                 // B: 3*64 rows x 8 chunks
            const int idx = tid + i * 256;
            const int r = idx >> 3, c = idx & 7;
            const int g = r >> 6, rr = r & 63;
            cpa16(&Bs[r * GRU_PAD + c * 4],
                  &Whh_l[(size_t)(g * HD_ + n0 + rr) * HD_ + k0 + c * 4]);
        }
        asm volatile("cp.async.commit_group;");
    };

    issue(0);

    const int arow = wm * 64 + (lane & 7) + ((lane >> 3) & 1) * 8;
    const int akc  = ((lane >> 4) & 1) * 4;
    const int brow = wn * 16 + (lane & 7) + ((lane >> 4) & 1) * 8;
    const int bkc  = ((lane >> 3) & 1) * 4;

    const int nIter = HD_ / GRU_BK;  // 32
    for (int it = 0; it < nIter; it++) {
        if (it + 1 < nIter) {
            issue(it + 1);
            asm volatile("cp.async.wait_group 1;");
        } else {
            asm volatile("cp.async.wait_group 0;");
        }
        __syncthreads();
        float* As = smem + (it & 1) * GRU_STAGE;
        float* Bs = As + 128 * GRU_PAD;
#pragma unroll
        for (int ks = 0; ks < 4; ks++) {
            uint32_t af[4][4];
#pragma unroll
            for (int mt = 0; mt < 4; mt++)
                ldsm4(af[mt], &As[(arow + mt * 16) * GRU_PAD + ks * 8 + akc]);
            uint32_t bf[3][4];
#pragma unroll
            for (int g = 0; g < 3; g++) {
                ldsm4(bf[g], &Bs[(g * 64 + brow) * GRU_PAD + ks * 8 + bkc]);
#pragma unroll
                for (int q = 0; q < 4; q++)   // weights: rna round to tf32 (unbiased)
                    bf[g][q] = __float_as_uint(to_tf32(__uint_as_float(bf[g][q])));
            }
#pragma unroll
            for (int g = 0; g < 3; g++)
#pragma unroll
                for (int mt = 0; mt < 4; mt++)
#pragma unroll
                    for (int nt = 0; nt < 2; nt++)
                        mma8(acc[g][mt * 2 + nt], af[mt], bf[g][nt * 2], bf[g][nt * 2 + 1]);
        }
        __syncthreads();
    }

    // ---- fused gate epilogue ----
    const float STD = 1.0025031276057952f; // exp(0.5*0.005)
#pragma unroll
    for (int nt = 0; nt < 2; nt++) {
        const int c = n0 + wn * 16 + nt * 8 + 2 * (lane & 3);
        const float2 br = *reinterpret_cast<const float2*>(&bhh_l[c]);
        const float2 bu = *reinterpret_cast<const float2*>(&bhh_l[HD_ + c]);
        const float2 bn = *reinterpret_cast<const float2*>(&bhh_l[2 * HD_ + c]);
#pragma unroll
        for (int mt = 0; mt < 4; mt++) {
#pragma unroll
            for (int half = 0; half < 2; half++) {
                const int r = m0 + wm * 64 + mt * 16 + (lane >> 2) + half * 8;
                const size_t o3 = (size_t)r * H3 + c;
                const size_t o1 = (size_t)r * HD_ + c;
                const float2 xr = *reinterpret_cast<const float2*>(&gx_l[o3]);
                const float2 xu = *reinterpret_cast<const float2*>(&gx_l[o3 + HD_]);
                const float2 xn = *reinterpret_cast<const float2*>(&gx_l[o3 + 2 * HD_]);
                const float2 hp = *reinterpret_cast<const float2*>(&h[o1]);
                const float2 ep = *reinterpret_cast<const float2*>(&eps_l[o1]);
                const float hr0 = acc[0][mt * 2 + nt][half * 2 + 0] + br.x;
                const float hr1 = acc[0][mt * 2 + nt][half * 2 + 1] + br.y;
                const float hu0 = acc[1][mt * 2 + nt][half * 2 + 0] + bu.x;
                const float hu1 = acc[1][mt * 2 + nt][half * 2 + 1] + bu.y;
                const float hn0 = acc[2][mt * 2 + nt][half * 2 + 0] + bn.x;
                const float hn1 = acc[2][mt * 2 + nt][half * 2 + 1] + bn.y;
                const float r0 = sigf(xr.x + hr0), r1 = sigf(xr.y + hr1);
                const float u0 = sigf(xu.x + hu0), u1 = sigf(xu.y + hu1);
                const float n0v = tanhf(xn.x + r0 * hn0), n1v = tanhf(xn.y + r1 * hn1);
                float2 o;
                o.x = to_tf32((1.0f - u0) * n0v + u0 * hp.x + STD * ep.x);
                o.y = to_tf32((1.0f - u1) * n1v + u1 * hp.y + STD * ep.y);
                *reinterpret_cast<float2*>(&zt_out[o1]) = o;
            }
        }
    }
}

// ============================================================================
// Generic TF32 NT GEMM (unchanged from R3, works): modes 1..4
// ============================================================================
struct GP {
    const float* A;    size_t sA; int lda;
    const float* Bm;   size_t sB; int ldb;
    float*       C;    size_t sC; int ldc;
    const float* bias; size_t sBias;
    const float* tmat;
    int M, N, K, mode;
};

template <bool VECB>
__global__ __launch_bounds__(256)
void gemm_tf32(GP p) {
    constexpr int BK = 16;
    __shared__ float As[128][20];
    __shared__ float Bs[128][20];

    const int l = blockIdx.z;
    const float* A    = p.A    + (size_t)l * p.sA;
    const float* Bm   = p.Bm   + (size_t)l * p.sB;
    const float* bias = p.bias + (size_t)l * p.sBias;

    const int m0 = blockIdx.y * 128;
    const int n0 = blockIdx.x * 128;
    const int tid = threadIdx.x;
    const int lane = tid & 31;
    const int warp = tid >> 5;
    const int wm = warp >> 2;
    const int wn = warp & 3;

    const int srow = tid >> 2;
    const int scol = (tid & 3) * 4;

    float acc[16][4];
#pragma unroll
    for (int i = 0; i < 16; i++)
        acc[i][0] = acc[i][1] = acc[i][2] = acc[i][3] = 0.0f;

    float ra[2][4], rb[2][4];
    const int nIter = p.K / BK;

    auto gload = [&](int k0) {
#pragma unroll
        for (int h = 0; h < 2; h++) {
            const int m = m0 + srow + h * 64;
            float4 v = *reinterpret_cast<const float4*>(&A[(size_t)m * p.lda + k0 + scol]);
            ra[h][0] = to_tf32(v.x); ra[h][1] = to_tf32(v.y);
            ra[h][2] = to_tf32(v.z); ra[h][3] = to_tf32(v.w);
            const int n = n0 + srow + h * 64;
            if (n < p.N) {
                const float* q = &Bm[(size_t)n * p.ldb + k0 + scol];
                if (VECB) {
                    float4 w = *reinterpret_cast<const float4*>(q);
                    rb[h][0] = to_tf32(w.x); rb[h][1] = to_tf32(w.y);
                    rb[h][2] = to_tf32(w.z); rb[h][3] = to_tf32(w.w);
                } else {
                    rb[h][0] = to_tf32(q[0]); rb[h][1] = to_tf32(q[1]);
                    rb[h][2] = to_tf32(q[2]); rb[h][3] = to_tf32(q[3]);
                }
            } else {
                rb[h][0] = rb[h][1] = rb[h][2] = rb[h][3] = 0.0f;
            }
        }
    };
    auto sstore = [&]() {
#pragma unroll
        for (int h = 0; h < 2; h++) {
            *reinterpret_cast<float4*>(&As[srow + h * 64][scol]) =
                make_float4(ra[h][0], ra[h][1], ra[h][2], ra[h][3]);
            *reinterpret_cast<float4*>(&Bs[srow + h * 64][scol]) =
                make_float4(rb[h][0], rb[h][1], rb[h][2], rb[h][3]);
        }
    };

    gload(0);
    sstore();
    __syncthreads();

    const int arow = wm * 64 + (lane & 7) + ((lane >> 3) & 1) * 8;
    const int akc0 = ((lane >> 4) & 1) * 4;
    const int brow = wn * 32 + (lane & 7) + ((lane >> 4) & 1) * 8;
    const int bkc0 = ((lane >> 3) & 1) * 4;

    for (int it = 0; it < nIter; it++) {
        if (it + 1 < nIter) gload((it + 1) * BK);
#pragma unroll
        for (int ks = 0; ks < 2; ks++) {
            uint32_t af[4][4], bf[2][4];
#pragma unroll
            for (int mt = 0; mt < 4; mt++)
                ldsm4(af[mt], &As[arow + mt * 16][ks * 8 + akc0]);
#pragma unroll
            for (int bt = 0; bt < 2; bt++)
                ldsm4(bf[bt], &Bs[brow + bt * 16][ks * 8 + bkc0]);
#pragma unroll
            for (int mt = 0; mt < 4; mt++)
#pragma unroll
                for (int nt = 0; nt < 4; nt++)
                    mma8(acc[mt * 4 + nt], af[mt],
                         bf[nt >> 1][(nt & 1) * 2], bf[nt >> 1][(nt & 1) * 2 + 1]);
        }
        if (it + 1 < nIter) {
            __syncthreads();
            sstore();
            __syncthreads();
        }
    }

    float* C = p.C + (size_t)l * p.sC;
#pragma unroll
    for (int mt = 0; mt < 4; mt++) {
        const int r = m0 + wm * 64 + mt * 16 + (lane >> 2);
#pragma unroll
        for (int nt = 0; nt < 4; nt++) {
            const int c = n0 + wn * 32 + nt * 8 + 2 * (lane & 3);
            float* a = acc[mt * 4 + nt];
            if (p.mode == 4 && c >= p.N) continue;

            float b0 = bias[c], b1 = bias[c + 1];
            float v00 = a[0] + b0, v01 = a[1] + b1;
            float v10 = a[2] + b0, v11 = a[3] + b1;

            if (p.mode == 1) {
                const float w0 = Bm[(size_t)c * p.ldb + p.K];
                const float w1 = Bm[(size_t)(c + 1) * p.ldb + p.K];
                const float t0 = p.tmat[(size_t)r * L_ + l];
                const float t1 = p.tmat[(size_t)(r + 8) * L_ + l];
                v00 += t0 * w0; v01 += t0 * w1;
                v10 += t1 * w0; v11 += t1 * w1;
            } else if (p.mode == 2) {
                v00 = fmaxf(v00, 0.f); v01 = fmaxf(v01, 0.f);
                v10 = fmaxf(v10, 0.f); v11 = fmaxf(v11, 0.f);
            } else if (p.mode == 3) {
                v00 = sigf(v00); v01 = sigf(v01);
                v10 = sigf(v10); v11 = sigf(v11);
            } else if (p.mode == 4) {
                v00 = sigf(v00); v01 = sigf(v01);
                v10 = sigf(v10); v11 = sigf(v11);
                p.C[((size_t)c       * B_ + r)     * L_ + l] = v00;
                p.C[((size_t)(c + 1) * B_ + r)     * L_ + l] = v01;
                p.C[((size_t)c       * B_ + r + 8) * L_ + l] = v10;
                p.C[((size_t)(c + 1) * B_ + r + 8) * L_ + l] = v11;
                continue;
            }
            *reinterpret_cast<float2*>(&C[(size_t)r * p.ldc + c]) = make_float2(v00, v01);
            *reinterpret_cast<float2*>(&C[(size_t)(r + 8) * p.ldc + c]) = make_float2(v10, v11);
        }
    }
}

// ---------------- first-step gate (h0 = 0, gh = bhh) -------------------------
__device__ __forceinline__ float gru_one0(float xr, float xu, float xn,
                                          float hr, float hu, float hn, float ep) {
    const float STD = 1.0025031276057952f;
    float r = sigf(xr + hr);
    float u = sigf(xu + hu);
    float n = tanhf(xn + r * hn);
    return (1.0f - u) * n + STD * ep;
}

__global__ void gru_gate0(const float* __restrict__ gx, const float* __restrict__ bhh,
                          const float* __restrict__ eps, float* __restrict__ hnew) {
    const int i4 = blockIdx.x * blockDim.x + threadIdx.x;
    if (i4 >= B_ * HD_ / 4) return;
    const int idx = i4 << 2;
    const int b = idx >> 10;
    const int j = idx & (HD_ - 1);
    const size_t o3 = (size_t)b * H3 + j;
    const size_t o1 = (size_t)b * HD_ + j;

    float4 xr = *reinterpret_cast<const float4*>(&gx[o3]);
    float4 xu = *reinterpret_cast<const float4*>(&gx[o3 + HD_]);
    float4 xn = *reinterpret_cast<const float4*>(&gx[o3 + 2 * HD_]);
    float4 hr = *reinterpret_cast<const float4*>(&bhh[j]);
    float4 hu = *reinterpret_cast<const float4*>(&bhh[j + HD_]);
    float4 hn = *reinterpret_cast<const float4*>(&bhh[j + 2 * HD_]);
    float4 ep = *reinterpret_cast<const float4*>(&eps[o1]);

    float4 o;
    o.x = to_tf32(gru_one0(xr.x, xu.x, xn.x, hr.x, hu.x, hn.x, ep.x));
    o.y = to_tf32(gru_one0(xr.y, xu.y, xn.y, hr.y, hu.y, hn.y, ep.y));
    o.z = to_tf32(gru_one0(xr.z, xu.z, xn.z, hr.z, hu.z, hn.z, ep.z));
    o.w = to_tf32(gru_one0(xr.w, xu.w, xn.w, hr.w, hu.w, hn.w, ep.w));
    *reinterpret_cast<float4*>(&hnew[o1]) = o;
}

// ---------------- launch ----------------------------------------------------
extern "C" void kernel_launch(void* const* d_in, const int* in_sizes, int n_in,
                              void* d_out, int out_size) {
    const float* z    = (const float*)d_in[0];
    const float* t    = (const float*)d_in[1];
    const float* eps  = (const float*)d_in[2];
    const float* Wih  = (const float*)d_in[3];
    const float* Whh  = (const float*)d_in[4];
    const float* bih  = (const float*)d_in[5];
    const float* bhh  = (const float*)d_in[6];
    const float* pW1  = (const float*)d_in[7];
    const float* pb1  = (const float*)d_in[8];
    const float* pW2  = (const float*)d_in[9];
    const float* pb2  = (const float*)d_in[10];
    const float* recW = (const float*)d_in[11];
    const float* recb = (const float*)d_in[12];

    float* out       = (float*)d_out;
    float* out_recon = out;                          // [B, XD]
    float* out_pred  = out + (size_t)B_ * XD_;       // [NW, B, L]

    float *GX, *ZT, *A1;
    cudaGetSymbolAddress((void**)&GX, g_GXALL);
    cudaGetSymbolAddress((void**)&ZT, g_ZT);
    cudaGetSymbolAddress((void**)&A1, g_A1);

    static bool attr_done = false;
    if (!attr_done) {
        cudaFuncSetAttribute(gemm_gru, cudaFuncAttributeMaxDynamicSharedMemorySize, GRU_SMEM);
        attr_done = true;
    }

    // 1) gx_all[l] = z @ WihZ_l^T + t[:,l] ⊗ Wih_l[:,ZD] + bih_l   (L-parallel)
    {
        GP p{};
        p.A = z;   p.sA = 0;                        p.lda = ZD_;
        p.Bm = Wih; p.sB = (size_t)H3 * (ZD_ + 1);  p.ldb = ZD_ + 1;
        p.C = GX;  p.sC = (size_t)B_ * H3;          p.ldc = H3;
        p.bias = bih; p.sBias = H3;
        p.tmat = t;
        p.M = B_; p.N = H3; p.K = ZD_; p.mode = 1;
        gemm_tf32<false><<<dim3(H3 / 128, B_ / 128, L_), 256>>>(p);
    }

    // 2) sequential GRU scan: fused GEMM + gates per step
    gru_gate0<<<(B_ * HD_ / 4 + 255) / 256, 256>>>(GX, bhh, eps, ZT);
    for (int l = 1; l < L_; l++) {
        gemm_gru<<<dim3(HD_ / 64, B_ / 128), 256, GRU_SMEM>>>(
            ZT + (size_t)(l - 1) * B_ * HD_,
            Whh + (size_t)l * H3 * HD_,
            bhh + (size_t)l * H3,
            GX + (size_t)l * B_ * H3,
            eps + (size_t)l * B_ * HD_,
            ZT + (size_t)l * B_ * HD_);
    }

    // 3) MLP hidden: A1[l] = relu(z_theta[l] @ pW1_l^T + pb1_l)   (L-parallel)
    {
        GP p{};
        p.A = ZT;  p.sA = (size_t)B_ * HD_;  p.lda = HD_;
        p.Bm = pW1; p.sB = (size_t)HD_ * HD_; p.ldb = HD_;
        p.C = A1;  p.sC = (size_t)B_ * HD_;  p.ldc = HD_;
        p.bias = pb1; p.sBias = HD_;
        p.M = B_; p.N = HD_; p.K = HD_; p.mode = 2;
        gemm_tf32<true><<<dim3(HD_ / 128, B_ / 128, L_), 256>>>(p);
    }

    // 4) preds: sigmoid(A1[l] @ pW2_l^T + pb2_l), stored [NW, B, L]   (L-parallel)
    {
        GP p{};
        p.A = A1;  p.sA = (size_t)B_ * HD_;  p.lda = HD_;
        p.Bm = pW2; p.sB = (size_t)NW_ * HD_; p.ldb = HD_;
        p.C = out_pred; p.sC = 0; p.ldc = 0;
        p.bias = pb2; p.sBias = NW_;
        p.M = B_; p.N = NW_; p.K = HD_; p.mode = 4;
        gemm_tf32<true><<<dim3(1, B_ / 128, L_), 256>>>(p);
    }

    // 5) recon = sigmoid(hT @ recW^T + recb)
    {
        GP p{};
        p.A = ZT + (size_t)(L_ - 1) * B_ * HD_; p.sA = 0; p.lda = HD_;
        p.Bm = recW; p.sB = 0; p.ldb = HD_;
        p.C = out_recon; p.sC = 0; p.ldc = XD_;
        p.bias = recb; p.sBias = 0;
        p.M = B_; p.N = XD_; p.K = HD_; p.mode = 3;
        gemm_tf32<true><<<dim3(XD_ / 128, B_ / 128, 1), 256>>>(p);
    }
}

// round 10
// speedup vs baseline: 3.4867x; 1.1065x over previous
#include <cuda_runtime.h>
#include <cmath>
#include <cstdint>

// Problem constants
#define B_   1024
#define ZD_  256
#define HD_  1024
#define L_   32
#define NW_  64
#define XD_  1024
#define H3   3072   // 3*HD

// ---------------- scratch (device globals: no runtime allocation) ----------
__device__ float g_GXALL[(size_t)L_ * B_ * H3];    // gx for all steps
__device__ float g_ZT[(size_t)L_ * B_ * HD_];      // z_theta per step (tf32)
__device__ float g_A1[(size_t)L_ * B_ * HD_];      // MLP hidden per step (tf32)
__device__ float g_WIH[(size_t)L_ * H3 * ZD_];     // repacked Wih[:, :256] (tf32)
__device__ float g_TW[(size_t)L_ * H3];            // Wih[:, 256] t-column (fp32)
__device__ float g_WHH[(size_t)L_ * H3 * HD_];     // Whh (tf32)
__device__ float g_W1[(size_t)L_ * HD_ * HD_];     // pW1 (tf32)
__device__ float g_W2[(size_t)L_ * NW_ * HD_];     // pW2 (tf32)
__device__ float g_WREC[(size_t)XD_ * HD_];        // recW (tf32)
__device__ float g_Z[(size_t)B_ * ZD_];            // z (tf32)

// ---------------- helpers ---------------------------------------------------
__device__ __forceinline__ float sigf(float x) { return 1.0f / (1.0f + expf(-x)); }

__device__ __forceinline__ float to_tf32(float x) {
    float r;
    asm("cvt.rna.tf32.f32 %0, %1;" : "=f"(r) : "f"(x));
    return r;
}

__device__ __forceinline__ void ldsm4(uint32_t* r, const void* p) {
    uint32_t a = (uint32_t)__cvta_generic_to_shared(p);
    asm volatile("ldmatrix.sync.aligned.m8n8.x4.shared.b16 {%0,%1,%2,%3}, [%4];"
                 : "=r"(r[0]), "=r"(r[1]), "=r"(r[2]), "=r"(r[3]) : "r"(a));
}

__device__ __forceinline__ void mma8(float* c, const uint32_t* a, uint32_t b0, uint32_t b1) {
    asm volatile("mma.sync.aligned.m16n8k8.row.col.f32.tf32.tf32.f32 "
                 "{%0,%1,%2,%3}, {%4,%5,%6,%7}, {%8,%9}, {%0,%1,%2,%3};"
                 : "+f"(c[0]), "+f"(c[1]), "+f"(c[2]), "+f"(c[3])
                 : "r"(a[0]), "r"(a[1]), "r"(a[2]), "r"(a[3]), "r"(b0), "r"(b1));
}

__device__ __forceinline__ void cpa16(void* dst, const void* src) {
    uint32_t d = (uint32_t)__cvta_generic_to_shared(dst);
    asm volatile("cp.async.cg.shared.global [%0], [%1], 16;" :: "r"(d), "l"(src));
}

// ---------------- prep kernels ----------------------------------------------
__global__ void cvt4(const float4* __restrict__ in, float4* __restrict__ out, int n4) {
    int i = blockIdx.x * blockDim.x + threadIdx.x;
    if (i >= n4) return;
    float4 v = in[i];
    v.x = to_tf32(v.x); v.y = to_tf32(v.y); v.z = to_tf32(v.z); v.w = to_tf32(v.w);
    out[i] = v;
}

__global__ void repack_wih(const float* __restrict__ Wih, float* __restrict__ out,
                           float* __restrict__ tw) {
    int q = blockIdx.x * blockDim.x + threadIdx.x;   // over L*H3*64 float4s
    if (q >= L_ * H3 * 64) return;
    const int j = q >> 6;            // row in [0, L*H3)
    const int k = (q & 63) * 4;
    const float* s = Wih + (size_t)j * (ZD_ + 1) + k;
    float4 v;
    v.x = to_tf32(s[0]); v.y = to_tf32(s[1]); v.z = to_tf32(s[2]); v.w = to_tf32(s[3]);
    *reinterpret_cast<float4*>(&out[(size_t)j * ZD_ + k]) = v;
    if ((q & 63) == 0) tw[j] = Wih[(size_t)j * (ZD_ + 1) + ZD_];
}

// ============================================================================
// Fused GRU step: cp.async 3-stage, BK=32, 128x(64x3 gates) tile, 128 CTAs.
// All inputs already tf32-rounded — no cvt in hot loop.
// ============================================================================
#define GRU_BK    32
#define GRU_PAD   36
#define GRU_STG   ((128 + 192) * GRU_PAD)   // floats per stage = 11520
#define GRU_SMEM  (3 * GRU_STG * 4)         // 138240 bytes

__global__ __launch_bounds__(256)
void gemm_gru(const float* __restrict__ h,      // [B, HD] prev z_theta (tf32)
              const float* __restrict__ Whh_l,  // [3*HD, HD] (tf32)
              const float* __restrict__ bhh_l,  // [3*HD]
              const float* __restrict__ gx_l,   // [B, 3*HD]
              const float* __restrict__ eps_l,  // [B, HD]
              float* __restrict__ zt_out)       // [B, HD]
{
    extern __shared__ float smem[];
    const int n0 = blockIdx.x * 64;
    const int m0 = blockIdx.y * 128;
    const int tid = threadIdx.x;
    const int lane = tid & 31;
    const int warp = tid >> 5;
    const int wm = warp >> 2;
    const int wn = warp & 3;
    const int nIter = HD_ / GRU_BK;  // 32

    float acc[3][8][4];
#pragma unroll
    for (int g = 0; g < 3; g++)
#pragma unroll
        for (int i = 0; i < 8; i++)
            acc[g][i][0] = acc[g][i][1] = acc[g][i][2] = acc[g][i][3] = 0.0f;

    auto issue = [&](int it) {
        if (it < nIter) {
            float* As = smem + (it % 3) * GRU_STG;
            float* Bs = As + 128 * GRU_PAD;
            const int k0 = it * GRU_BK;
#pragma unroll
            for (int i = 0; i < 4; i++) {                 // A: 128 rows x 8 chunks
                const int idx = tid + i * 256;
                const int r = idx >> 3, c = idx & 7;
                cpa16(&As[r * GRU_PAD + c * 4], &h[(size_t)(m0 + r) * HD_ + k0 + c * 4]);
            }
#pragma unroll
            for (int i = 0; i < 6; i++) {                 // B: 192 rows x 8 chunks
                const int idx = tid + i * 256;
                const int r = idx >> 3, c = idx & 7;
                const int g = r >> 6, rr = r & 63;
                cpa16(&Bs[r * GRU_PAD + c * 4],
                      &Whh_l[(size_t)(g * HD_ + n0 + rr) * HD_ + k0 + c * 4]);
            }
        }
        asm volatile("cp.async.commit_group;");
    };

    issue(0);
    issue(1);

    const int arow = wm * 64 + (lane & 7) + ((lane >> 3) & 1) * 8;
    const int akc  = ((lane >> 4) & 1) * 4;
    const int brow = wn * 16 + (lane & 7) + ((lane >> 4) & 1) * 8;
    const int bkc  = ((lane >> 3) & 1) * 4;

    for (int it = 0; it < nIter; it++) {
        asm volatile("cp.async.wait_group 1;");
        __syncthreads();
        issue(it + 2);
        float* As = smem + (it % 3) * GRU_STG;
        float* Bs = As + 128 * GRU_PAD;
#pragma unroll
        for (int ks = 0; ks < 4; ks++) {
            uint32_t af[4][4], bf[3][4];
#pragma unroll
            for (int mt = 0; mt < 4; mt++)
                ldsm4(af[mt], &As[(arow + mt * 16) * GRU_PAD + ks * 8 + akc]);
#pragma unroll
            for (int g = 0; g < 3; g++)
                ldsm4(bf[g], &Bs[(g * 64 + brow) * GRU_PAD + ks * 8 + bkc]);
#pragma unroll
            for (int g = 0; g < 3; g++)
#pragma unroll
                for (int mt = 0; mt < 4; mt++)
#pragma unroll
                    for (int nt = 0; nt < 2; nt++)
                        mma8(acc[g][mt * 2 + nt], af[mt], bf[g][nt * 2], bf[g][nt * 2 + 1]);
        }
    }

    // ---- fused gate epilogue ----
    const float STD = 1.0025031276057952f; // exp(0.5*0.005)
#pragma unroll
    for (int nt = 0; nt < 2; nt++) {
        const int c = n0 + wn * 16 + nt * 8 + 2 * (lane & 3);
        const float2 br = *reinterpret_cast<const float2*>(&bhh_l[c]);
        const float2 bu = *reinterpret_cast<const float2*>(&bhh_l[HD_ + c]);
        const float2 bn = *reinterpret_cast<const float2*>(&bhh_l[2 * HD_ + c]);
#pragma unroll
        for (int mt = 0; mt < 4; mt++) {
#pragma unroll
            for (int half = 0; half < 2; half++) {
                const int r = m0 + wm * 64 + mt * 16 + (lane >> 2) + half * 8;
                const size_t o3 = (size_t)r * H3 + c;
                const size_t o1 = (size_t)r * HD_ + c;
                const float2 xr = *reinterpret_cast<const float2*>(&gx_l[o3]);
                const float2 xu = *reinterpret_cast<const float2*>(&gx_l[o3 + HD_]);
                const float2 xn = *reinterpret_cast<const float2*>(&gx_l[o3 + 2 * HD_]);
                const float2 hp = *reinterpret_cast<const float2*>(&h[o1]);
                const float2 ep = *reinterpret_cast<const float2*>(&eps_l[o1]);
                const float hr0 = acc[0][mt * 2 + nt][half * 2 + 0] + br.x;
                const float hr1 = acc[0][mt * 2 + nt][half * 2 + 1] + br.y;
                const float hu0 = acc[1][mt * 2 + nt][half * 2 + 0] + bu.x;
                const float hu1 = acc[1][mt * 2 + nt][half * 2 + 1] + bu.y;
                const float hn0 = acc[2][mt * 2 + nt][half * 2 + 0] + bn.x;
                const float hn1 = acc[2][mt * 2 + nt][half * 2 + 1] + bn.y;
                const float r0 = sigf(xr.x + hr0), r1 = sigf(xr.y + hr1);
                const float u0 = sigf(xu.x + hu0), u1 = sigf(xu.y + hu1);
                const float n0v = tanhf(xn.x + r0 * hn0), n1v = tanhf(xn.y + r1 * hn1);
                float2 o;
                o.x = to_tf32((1.0f - u0) * n0v + u0 * hp.x + STD * ep.x);
                o.y = to_tf32((1.0f - u1) * n1v + u1 * hp.y + STD * ep.y);
                *reinterpret_cast<float2*>(&zt_out[o1]) = o;
            }
        }
    }
}

// ============================================================================
// Generic TF32 NT GEMM, cp.async 3-stage, BK=16, 128x128 tile.
// Inputs must be pre-rounded to tf32. Modes as before.
// ============================================================================
#define CA_PAD  20
#define CA_STG  ((128 + 128) * CA_PAD)   // 5120 floats per stage
#define CA_SMEM (3 * CA_STG * 4)         // 61440 bytes

struct GP {
    const float* A;    size_t sA; int lda;
    const float* Bm;   size_t sB; int ldb;
    float*       C;    size_t sC; int ldc;
    const float* bias; size_t sBias;
    const float* tw;                       // packed t-col weights [L, H3] (mode 1)
    const float* tmat;                     // t [B, L] (mode 1)
    int M, N, K, mode;
    // 1: C = acc+bias+t[m,l]*tw[c]; 2: tf32(relu(acc+bias));
    // 3: sigmoid(acc+bias); 4: out[(c*B+m)*L+l] = sigmoid(acc+bias)
};

__global__ __launch_bounds__(256)
void gemm_ca(GP p) {
    extern __shared__ float smem[];
    const int l = blockIdx.z;
    const float* A    = p.A    + (size_t)l * p.sA;
    const float* Bm   = p.Bm   + (size_t)l * p.sB;
    const float* bias = p.bias + (size_t)l * p.sBias;

    const int m0 = blockIdx.y * 128;
    const int n0 = blockIdx.x * 128;
    const int tid = threadIdx.x;
    const int lane = tid & 31;
    const int warp = tid >> 5;
    const int wm = warp >> 2;
    const int wn = warp & 3;
    const int nIter = p.K / 16;

    float acc[16][4];
#pragma unroll
    for (int i = 0; i < 16; i++)
        acc[i][0] = acc[i][1] = acc[i][2] = acc[i][3] = 0.0f;

    auto issue = [&](int it) {
        if (it < nIter) {
            float* As = smem + (it % 3) * CA_STG;
            float* Bs = As + 128 * CA_PAD;
            const int k0 = it * 16;
#pragma unroll
            for (int i = 0; i < 2; i++) {
                const int idx = tid + i * 256;
                const int r = idx >> 2, c = idx & 3;
                cpa16(&As[r * CA_PAD + c * 4], &A[(size_t)(m0 + r) * p.lda + k0 + c * 4]);
            }
#pragma unroll
            for (int i = 0; i < 2; i++) {
                const int idx = tid + i * 256;
                const int r = idx >> 2, c = idx & 3;
                const int n = min(n0 + r, p.N - 1);   // clamp: junk rows feed skipped cols
                cpa16(&Bs[r * CA_PAD + c * 4], &Bm[(size_t)n * p.ldb + k0 + c * 4]);
            }
        }
        asm volatile("cp.async.commit_group;");
    };

    issue(0);
    issue(1);

    const int arow = wm * 64 + (lane & 7) + ((lane >> 3) & 1) * 8;
    const int akc0 = ((lane >> 4) & 1) * 4;
    const int brow = wn * 32 + (lane & 7) + ((lane >> 4) & 1) * 8;
    const int bkc0 = ((lane >> 3) & 1) * 4;

    for (int it = 0; it < nIter; it++) {
        asm volatile("cp.async.wait_group 1;");
        __syncthreads();
        issue(it + 2);
        float* As = smem + (it % 3) * CA_STG;
        float* Bs = As + 128 * CA_PAD;
#pragma unroll
        for (int ks = 0; ks < 2; ks++) {
            uint32_t af[4][4], bf[2][4];
#pragma unroll
            for (int mt = 0; mt < 4; mt++)
                ldsm4(af[mt], &As[(arow + mt * 16) * CA_PAD + ks * 8 + akc0]);
#pragma unroll
            for (int bt = 0; bt < 2; bt++)
                ldsm4(bf[bt], &Bs[(brow + bt * 16) * CA_PAD + ks * 8 + bkc0]);
#pragma unroll
            for (int mt = 0; mt < 4; mt++)
#pragma unroll
                for (int nt = 0; nt < 4; nt++)
                    mma8(acc[mt * 4 + nt], af[mt],
                         bf[nt >> 1][(nt & 1) * 2], bf[nt >> 1][(nt & 1) * 2 + 1]);
        }
    }

    float* C = p.C + (size_t)l * p.sC;
#pragma unroll
    for (int mt = 0; mt < 4; mt++) {
        const int r = m0 + wm * 64 + mt * 16 + (lane >> 2);
#pragma unroll
        for (int nt = 0; nt < 4; nt++) {
            const int c = n0 + wn * 32 + nt * 8 + 2 * (lane & 3);
            float* a = acc[mt * 4 + nt];
            if (p.mode == 4 && c >= p.N) continue;

            float b0 = bias[c], b1 = bias[c + 1];
            float v00 = a[0] + b0, v01 = a[1] + b1;
            float v10 = a[2] + b0, v11 = a[3] + b1;

            if (p.mode == 1) {
                const float w0 = p.tw[(size_t)l * H3 + c];
                const float w1 = p.tw[(size_t)l * H3 + c + 1];
                const float t0 = p.tmat[(size_t)r * L_ + l];
                const float t1 = p.tmat[(size_t)(r + 8) * L_ + l];
                v00 += t0 * w0; v01 += t0 * w1;
                v10 += t1 * w0; v11 += t1 * w1;
            } else if (p.mode == 2) {
                v00 = to_tf32(fmaxf(v00, 0.f)); v01 = to_tf32(fmaxf(v01, 0.f));
                v10 = to_tf32(fmaxf(v10, 0.f)); v11 = to_tf32(fmaxf(v11, 0.f));
            } else if (p.mode == 3) {
                v00 = sigf(v00); v01 = sigf(v01);
                v10 = sigf(v10); v11 = sigf(v11);
            } else if (p.mode == 4) {
                v00 = sigf(v00); v01 = sigf(v01);
                v10 = sigf(v10); v11 = sigf(v11);
                p.C[((size_t)c       * B_ + r)     * L_ + l] = v00;
                p.C[((size_t)(c + 1) * B_ + r)     * L_ + l] = v01;
                p.C[((size_t)c       * B_ + r + 8) * L_ + l] = v10;
                p.C[((size_t)(c + 1) * B_ + r + 8) * L_ + l] = v11;
                continue;
            }
            *reinterpret_cast<float2*>(&C[(size_t)r * p.ldc + c]) = make_float2(v00, v01);
            *reinterpret_cast<float2*>(&C[(size_t)(r + 8) * p.ldc + c]) = make_float2(v10, v11);
        }
    }
}

// ---------------- first-step gate (h0 = 0, gh = bhh) -------------------------
__device__ __forceinline__ float gru_one0(float xr, float xu, float xn,
                                          float hr, float hu, float hn, float ep) {
    const float STD = 1.0025031276057952f;
    float r = sigf(xr + hr);
    float u = sigf(xu + hu);
    float n = tanhf(xn + r * hn);
    return (1.0f - u) * n + STD * ep;
}

__global__ void gru_gate0(const float* __restrict__ gx, const float* __restrict__ bhh,
                          const float* __restrict__ eps, float* __restrict__ hnew) {
    const int i4 = blockIdx.x * blockDim.x + threadIdx.x;
    if (i4 >= B_ * HD_ / 4) return;
    const int idx = i4 << 2;
    const int b = idx >> 10;
    const int j = idx & (HD_ - 1);
    const size_t o3 = (size_t)b * H3 + j;
    const size_t o1 = (size_t)b * HD_ + j;

    float4 xr = *reinterpret_cast<const float4*>(&gx[o3]);
    float4 xu = *reinterpret_cast<const float4*>(&gx[o3 + HD_]);
    float4 xn = *reinterpret_cast<const float4*>(&gx[o3 + 2 * HD_]);
    float4 hr = *reinterpret_cast<const float4*>(&bhh[j]);
    float4 hu = *reinterpret_cast<const float4*>(&bhh[j + HD_]);
    float4 hn = *reinterpret_cast<const float4*>(&bhh[j + 2 * HD_]);
    float4 ep = *reinterpret_cast<const float4*>(&eps[o1]);

    float4 o;
    o.x = to_tf32(gru_one0(xr.x, xu.x, xn.x, hr.x, hu.x, hn.x, ep.x));
    o.y = to_tf32(gru_one0(xr.y, xu.y, xn.y, hr.y, hu.y, hn.y, ep.y));
    o.z = to_tf32(gru_one0(xr.z, xu.z, xn.z, hr.z, hu.z, hn.z, ep.z));
    o.w = to_tf32(gru_one0(xr.w, xu.w, xn.w, hr.w, hu.w, hn.w, ep.w));
    *reinterpret_cast<float4*>(&hnew[o1]) = o;
}

// ---------------- launch ----------------------------------------------------
extern "C" void kernel_launch(void* const* d_in, const int* in_sizes, int n_in,
                              void* d_out, int out_size) {
    const float* z    = (const float*)d_in[0];
    const float* t    = (const float*)d_in[1];
    const float* eps  = (const float*)d_in[2];
    const float* Wih  = (const float*)d_in[3];
    const float* Whh  = (const float*)d_in[4];
    const float* bih  = (const float*)d_in[5];
    const float* bhh  = (const float*)d_in[6];
    const float* pW1  = (const float*)d_in[7];
    const float* pb1  = (const float*)d_in[8];
    const float* pW2  = (const float*)d_in[9];
    const float* pb2  = (const float*)d_in[10];
    const float* recW = (const float*)d_in[11];
    const float* recb = (const float*)d_in[12];

    float* out       = (float*)d_out;
    float* out_recon = out;                          // [B, XD]
    float* out_pred  = out + (size_t)B_ * XD_;       // [NW, B, L]

    float *GX, *ZT, *A1, *WIH, *TW, *WHH, *W1, *W2, *WREC, *Zc;
    cudaGetSymbolAddress((void**)&GX,   g_GXALL);
    cudaGetSymbolAddress((void**)&ZT,   g_ZT);
    cudaGetSymbolAddress((void**)&A1,   g_A1);
    cudaGetSymbolAddress((void**)&WIH,  g_WIH);
    cudaGetSymbolAddress((void**)&TW,   g_TW);
    cudaGetSymbolAddress((void**)&WHH,  g_WHH);
    cudaGetSymbolAddress((void**)&W1,   g_W1);
    cudaGetSymbolAddress((void**)&W2,   g_W2);
    cudaGetSymbolAddress((void**)&WREC, g_WREC);
    cudaGetSymbolAddress((void**)&Zc,   g_Z);

    cudaFuncSetAttribute(gemm_gru, cudaFuncAttributeMaxDynamicSharedMemorySize, GRU_SMEM);
    cudaFuncSetAttribute(gemm_ca,  cudaFuncAttributeMaxDynamicSharedMemorySize, CA_SMEM);

    // 0) prep: tf32-round + repack all GEMM operands
    {
        const int T = 256;
        int n;
        n = L_ * H3 * 64;                 repack_wih<<<(n + T - 1) / T, T>>>(Wih, WIH, TW);
        n = (B_ * ZD_) / 4;               cvt4<<<(n + T - 1) / T, T>>>((const float4*)z, (float4*)Zc, n);
        n = (int)(((size_t)L_ * H3 * HD_) / 4);  cvt4<<<(n + T - 1) / T, T>>>((const float4*)Whh, (float4*)WHH, n);
        n = (int)(((size_t)L_ * HD_ * HD_) / 4); cvt4<<<(n + T - 1) / T, T>>>((const float4*)pW1, (float4*)W1, n);
        n = (L_ * NW_ * HD_) / 4;         cvt4<<<(n + T - 1) / T, T>>>((const float4*)pW2, (float4*)W2, n);
        n = (XD_ * HD_) / 4;              cvt4<<<(n + T - 1) / T, T>>>((const float4*)recW, (float4*)WREC, n);
    }

    // 1) gx_all[l] = z @ WihZ_l^T + t[:,l] ⊗ tw_l + bih_l   (L-parallel)
    {
        GP p{};
        p.A = Zc;  p.sA = 0;                       p.lda = ZD_;
        p.Bm = WIH; p.sB = (size_t)H3 * ZD_;       p.ldb = ZD_;
        p.C = GX;  p.sC = (size_t)B_ * H3;         p.ldc = H3;
        p.bias = bih; p.sBias = H3;
        p.tw = TW; p.tmat = t;
        p.M = B_; p.N = H3; p.K = ZD_; p.mode = 1;
        gemm_ca<<<dim3(H3 / 128, B_ / 128, L_), 256, CA_SMEM>>>(p);
    }

    // 2) sequential GRU scan: fused GEMM + gates per step
    gru_gate0<<<(B_ * HD_ / 4 + 255) / 256, 256>>>(GX, bhh, eps, ZT);
    for (int l = 1; l < L_; l++) {
        gemm_gru<<<dim3(HD_ / 64, B_ / 128), 256, GRU_SMEM>>>(
            ZT + (size_t)(l - 1) * B_ * HD_,
            WHH + (size_t)l * H3 * HD_,
            bhh + (size_t)l * H3,
            GX + (size_t)l * B_ * H3,
            eps + (size_t)l * B_ * HD_,
            ZT + (size_t)l * B_ * HD_);
    }

    // 3) MLP hidden: A1[l] = tf32(relu(z_theta[l] @ pW1_l^T + pb1_l))   (L-parallel)
    {
        GP p{};
        p.A = ZT;  p.sA = (size_t)B_ * HD_;   p.lda = HD_;
        p.Bm = W1; p.sB = (size_t)HD_ * HD_;  p.ldb = HD_;
        p.C = A1;  p.sC = (size_t)B_ * HD_;   p.ldc = HD_;
        p.bias = pb1; p.sBias = HD_;
        p.M = B_; p.N = HD_; p.K = HD_; p.mode = 2;
        gemm_ca<<<dim3(HD_ / 128, B_ / 128, L_), 256, CA_SMEM>>>(p);
    }

    // 4) preds: sigmoid(A1[l] @ pW2_l^T + pb2_l), stored [NW, B, L]   (L-parallel)
    {
        GP p{};
        p.A = A1;  p.sA = (size_t)B_ * HD_;   p.lda = HD_;
        p.Bm = W2; p.sB = (size_t)NW_ * HD_;  p.ldb = HD_;
        p.C = out_pred; p.sC = 0; p.ldc = 0;
        p.bias = pb2; p.sBias = NW_;
        p.M = B_; p.N = NW_; p.K = HD_; p.mode = 4;
        gemm_ca<<<dim3(1, B_ / 128, L_), 256, CA_SMEM>>>(p);
    }

    // 5) recon = sigmoid(hT @ recW^T + recb)
    {
        GP p{};
        p.A = ZT + (size_t)(L_ - 1) * B_ * HD_; p.sA = 0; p.lda = HD_;
        p.Bm = WREC; p.sB = 0; p.ldb = HD_;
        p.C = out_recon; p.sC = 0; p.ldc = XD_;
        p.bias = recb; p.sBias = 0;
        p.M = B_; p.N = XD_; p.K = HD_; p.mode = 3;
        gemm_ca<<<dim3(XD_ / 128, B_ / 128, 1), 256, CA_SMEM>>>(p);
    }
}